// round 10
// baseline (speedup 1.0000x reference)
#include <cuda_runtime.h>
#include <cstdint>

// Problem constants
#define KV_LEN      4096
#define PAGE_SZ     16
#define BSZ         4
#define SEQ         512
#define HEADS       16
#define HDIM        128
#define PAGES       1024
#define PPS         256
#define SHIFT_PAGES 33
#define FIRST_NEW_PAGE 223
#define LAST_PAGE   255

// float4 geometry
#define HALF_F4  8192       // one kv half of a page
#define PAGE_F4  16384
#define SLOT_F4  512        // one token: 16*128/4
#define HEAD_F4  32
#define CHUNK_F4 1024       // eighth of a half: 2 slots (16 KB)

// log2(10000)/64
#define LOG2_THETA_OVER_64 0.2076205059304601486

// 16384 tasks of 16KB, 128-thread blocks, per-thread MLP=8, 12 CTAs/SM.
//   kv    = t & 1
//   chunk = (t>>1) & 7   (eighth of a half: 2 slots)
//   i     = t >> 4       (logical page 0..1023)
__global__ __launch_bounds__(128, 12) void kv_rotate_kernel(
    const float* __restrict__ knew,
    const float* __restrict__ vnew,
    const float* __restrict__ cache,
    const int*   __restrict__ pidx,
    float*       __restrict__ out)
{
    const int t     = blockIdx.x;
    const int kv    = t & 1;
    const int chunk = (t >> 1) & 7;
    const int i     = t >> 4;
    const int b     = i >> 8;
    const int p     = i & 255;
    const int tid   = threadIdx.x;

    const int dpage = __ldg(&pidx[i]);
    float4* dst = (float4*)out + (size_t)dpage * PAGE_F4 + kv * HALF_F4 + chunk * CHUNK_F4;

    // source selection (page-granular: SHIFT+SEQ = 33 pages)
    const float4* src;
    if (p < FIRST_NEW_PAGE) {
        const int spage = __ldg(&pidx[b * PPS + p + SHIFT_PAGES]);
        src = (const float4*)cache + (size_t)spage * PAGE_F4 + kv * HALF_F4 + chunk * CHUNK_F4;
    } else if (p == LAST_PAGE) {
        src = (const float4*)cache + (size_t)dpage * PAGE_F4 + kv * HALF_F4 + chunk * CHUNK_F4;
    } else {
        const float* base = kv ? vnew : knew;
        src = (const float4*)base
            + (size_t)(b * SEQ + (p - FIRST_NEW_PAGE) * PAGE_SZ) * SLOT_F4 + chunk * CHUNK_F4;
    }

    if (kv == 1) {
        // streaming copy: 1024 f4 by 128 threads, front-batched MLP=8
        float4 r[8];
        #pragma unroll
        for (int j = 0; j < 8; j++) r[j] = __ldcs(&src[tid + 128 * j]);
        #pragma unroll
        for (int j = 0; j < 8; j++) __stcs(&dst[tid + 128 * j], r[j]);
        return;
    }

    // ---- k chunk: rotate-half RoPE on 2 slots ----
    __shared__ __align__(16) float s_cos[2][64];
    __shared__ __align__(16) float s_sin[2][64];

    {
        // 2 slots * 64 freqs = 128 entries = exactly one per thread
        const int slot = tid >> 6;
        const int f    = tid & 63;
        const float invf = (float)exp2(-(double)f * LOG2_THETA_OVER_64);  // f32-rounded inv_freq
        const float ang  = (float)(p * PAGE_SZ + chunk * 2 + slot) * invf;
        float s, c;
        sincosf(ang, &s, &c);
        s_cos[slot][f] = c;
        s_sin[slot][f] = s;
    }
    __syncthreads();

    // 2 slots * 16 heads * 16 j = 512 units; thread owns heads {h0, h0+8} for its j.
    const int h0 = tid >> 4;          // 0..7
    const int j  = tid & 15;

    // front-batch all 8 loads (MLP=8)
    float4 a[2][2], bb[2][2];
    #pragma unroll
    for (int q = 0; q < 2; q++) {         // slot
        #pragma unroll
        for (int e = 0; e < 2; e++) {     // head group
            const float4* sp = src + q * SLOT_F4 + (h0 + 8 * e) * HEAD_F4 + j;
            a[q][e]  = __ldcs(&sp[0]);    // x1 (dims 4j..4j+3)
            bb[q][e] = __ldcs(&sp[16]);   // x2 (dims 64+4j..)
        }
    }

    #pragma unroll
    for (int q = 0; q < 2; q++) {
        const float4 c = *(const float4*)&s_cos[q][4 * j];
        const float4 s = *(const float4*)&s_sin[q][4 * j];
        #pragma unroll
        for (int e = 0; e < 2; e++) {
            float4 o1, o2;
            o1.x = a[q][e].x * c.x - bb[q][e].x * s.x;  o2.x = a[q][e].x * s.x + bb[q][e].x * c.x;
            o1.y = a[q][e].y * c.y - bb[q][e].y * s.y;  o2.y = a[q][e].y * s.y + bb[q][e].y * c.y;
            o1.z = a[q][e].z * c.z - bb[q][e].z * s.z;  o2.z = a[q][e].z * s.z + bb[q][e].z * c.z;
            o1.w = a[q][e].w * c.w - bb[q][e].w * s.w;  o2.w = a[q][e].w * s.w + bb[q][e].w * c.w;

            float4* dp = dst + q * SLOT_F4 + (h0 + 8 * e) * HEAD_F4 + j;
            __stcs(&dp[0],  o1);
            __stcs(&dp[16], o2);
        }
    }
}

extern "C" void kernel_launch(void* const* d_in, const int* in_sizes, int n_in,
                              void* d_out, int out_size) {
    const float* k     = (const float*)d_in[0];
    const float* v     = (const float*)d_in[1];
    const float* cache = (const float*)d_in[2];
    const int*   pidx  = (const int*)d_in[3];
    float*       out   = (float*)d_out;

    kv_rotate_kernel<<<PAGES * 16, 128>>>(k, v, cache, pidx, out);
}

// round 11
// speedup vs baseline: 1.0639x; 1.0639x over previous
#include <cuda_runtime.h>
#include <cstdint>

// Problem constants
#define KV_LEN      4096
#define PAGE_SZ     16
#define BSZ         4
#define SEQ         512
#define HEADS       16
#define HDIM        128
#define PAGES       1024
#define PPS         256
#define SHIFT_PAGES 33
#define FIRST_NEW_PAGE 223
#define LAST_PAGE   255

// float4 geometry
#define HALF_F4  8192       // one kv half of a page
#define PAGE_F4  16384
#define SLOT_F4  512        // one token: 16*128/4
#define HEAD_F4  32
#define CHUNK_F4 1024       // eighth of a half: 2 slots (16 KB)

// log2(10000)/64
#define LOG2_THETA_OVER_64 0.2076205059304601486

// 16384 tasks of 16KB, 128-thread blocks, per-thread MLP=8.
//   kv    = t & 1
//   chunk = (t>>1) & 7   (eighth of a half: 2 slots)
//   i     = t >> 4       (logical page 0..1023)
__global__ __launch_bounds__(128, 10) void kv_rotate_kernel(
    const float* __restrict__ knew,
    const float* __restrict__ vnew,
    const float* __restrict__ cache,
    const int*   __restrict__ pidx,
    float*       __restrict__ out)
{
    const int t     = blockIdx.x;
    const int kv    = t & 1;
    const int chunk = (t >> 1) & 7;
    const int i     = t >> 4;
    const int b     = i >> 8;
    const int p     = i & 255;
    const int tid   = threadIdx.x;

    const int dpage = __ldg(&pidx[i]);
    float4* dst = (float4*)out + (size_t)dpage * PAGE_F4 + kv * HALF_F4 + chunk * CHUNK_F4;

    // source selection (page-granular: SHIFT+SEQ = 33 pages)
    const float4* src;
    if (p < FIRST_NEW_PAGE) {
        const int spage = __ldg(&pidx[b * PPS + p + SHIFT_PAGES]);
        src = (const float4*)cache + (size_t)spage * PAGE_F4 + kv * HALF_F4 + chunk * CHUNK_F4;
    } else if (p == LAST_PAGE) {
        src = (const float4*)cache + (size_t)dpage * PAGE_F4 + kv * HALF_F4 + chunk * CHUNK_F4;
    } else {
        const float* base = kv ? vnew : knew;
        src = (const float4*)base
            + (size_t)(b * SEQ + (p - FIRST_NEW_PAGE) * PAGE_SZ) * SLOT_F4 + chunk * CHUNK_F4;
    }

    if (kv == 1) {
        // streaming copy: 1024 f4 by 128 threads, front-batched MLP=8
        float4 r[8];
        #pragma unroll
        for (int j = 0; j < 8; j++) r[j] = __ldcs(&src[tid + 128 * j]);
        #pragma unroll
        for (int j = 0; j < 8; j++) __stcs(&dst[tid + 128 * j], r[j]);
        return;
    }

    // ---- k chunk: rotate-half RoPE on 2 slots ----
    __shared__ __align__(16) float s_cos[2][64];
    __shared__ __align__(16) float s_sin[2][64];

    {
        // 2 slots * 64 freqs = 128 entries = exactly one per thread
        const int slot = tid >> 6;
        const int f    = tid & 63;
        const float invf = (float)exp2(-(double)f * LOG2_THETA_OVER_64);  // f32-rounded inv_freq
        const float ang  = (float)(p * PAGE_SZ + chunk * 2 + slot) * invf;
        float s, c;
        sincosf(ang, &s, &c);
        s_cos[slot][f] = c;
        s_sin[slot][f] = s;
    }
    __syncthreads();

    // 2 slots * 16 heads * 16 j = 512 units; thread owns heads {h0, h0+8} for its j.
    const int h0 = tid >> 4;          // 0..7
    const int j  = tid & 15;

    // front-batch all 8 loads (MLP=8)
    float4 a[2][2], bb[2][2];
    #pragma unroll
    for (int q = 0; q < 2; q++) {         // slot
        #pragma unroll
        for (int e = 0; e < 2; e++) {     // head group
            const float4* sp = src + q * SLOT_F4 + (h0 + 8 * e) * HEAD_F4 + j;
            a[q][e]  = __ldcs(&sp[0]);    // x1 (dims 4j..4j+3)
            bb[q][e] = __ldcs(&sp[16]);   // x2 (dims 64+4j..)
        }
    }

    #pragma unroll
    for (int q = 0; q < 2; q++) {
        const float4 c = *(const float4*)&s_cos[q][4 * j];
        const float4 s = *(const float4*)&s_sin[q][4 * j];
        #pragma unroll
        for (int e = 0; e < 2; e++) {
            float4 o1, o2;
            o1.x = a[q][e].x * c.x - bb[q][e].x * s.x;  o2.x = a[q][e].x * s.x + bb[q][e].x * c.x;
            o1.y = a[q][e].y * c.y - bb[q][e].y * s.y;  o2.y = a[q][e].y * s.y + bb[q][e].y * c.y;
            o1.z = a[q][e].z * c.z - bb[q][e].z * s.z;  o2.z = a[q][e].z * s.z + bb[q][e].z * c.z;
            o1.w = a[q][e].w * c.w - bb[q][e].w * s.w;  o2.w = a[q][e].w * s.w + bb[q][e].w * c.w;

            float4* dp = dst + q * SLOT_F4 + (h0 + 8 * e) * HEAD_F4 + j;
            __stcs(&dp[0],  o1);
            __stcs(&dp[16], o2);
        }
    }
}

extern "C" void kernel_launch(void* const* d_in, const int* in_sizes, int n_in,
                              void* d_out, int out_size) {
    const float* k     = (const float*)d_in[0];
    const float* v     = (const float*)d_in[1];
    const float* cache = (const float*)d_in[2];
    const int*   pidx  = (const int*)d_in[3];
    float*       out   = (float*)d_out;

    kv_rotate_kernel<<<PAGES * 16, 128>>>(k, v, cache, pidx, out);
}

// round 12
// speedup vs baseline: 1.0726x; 1.0082x over previous
#include <cuda_runtime.h>
#include <cstdint>

// Problem constants
#define KV_LEN      4096
#define PAGE_SZ     16
#define BSZ         4
#define SEQ         512
#define HEADS       16
#define HDIM        128
#define PAGES       1024
#define PPS         256
#define SHIFT_PAGES 33
#define FIRST_NEW_PAGE 223
#define LAST_PAGE   255

// float4 geometry
#define HALF_F4   8192      // one kv half of a page (128 KB)
#define PAGE_F4   16384
#define SLOT_F4   512       // one token: 16*128/4
#define HEAD_F4   32
#define CCHUNK_F4 2048      // copy chunk: quarter of v-half (32 KB, 4 slots)
#define RCHUNK_F4 1024      // rope chunk: eighth of k-half (16 KB, 2 slots)

#define NTASKS    12288     // 4096 copy (t%3==0) + 8192 rope (t%3==1,2)

// log2(10000)/64
#define LOG2_THETA_OVER_64 0.2076205059304601486

__global__ __launch_bounds__(128) void kv_rotate_kernel(
    const float* __restrict__ knew,
    const float* __restrict__ vnew,
    const float* __restrict__ cache,
    const int*   __restrict__ pidx,
    float*       __restrict__ out)
{
    const int t   = blockIdx.x;
    const int q3  = t / 3;              // mul-shift, cheap
    const int r3  = t - q3 * 3;
    const int tid = threadIdx.x;

    if (r3 == 0) {
        // ===== v-copy task: 32 KB, per-thread MLP=16 =====
        const int c     = q3;           // 0..4095
        const int i     = c >> 2;       // logical page
        const int chunk = c & 3;        // quarter of the v half
        const int b     = i >> 8;
        const int p     = i & 255;

        const int dpage = __ldg(&pidx[i]);
        float4* dst = (float4*)out + (size_t)dpage * PAGE_F4 + HALF_F4 + chunk * CCHUNK_F4;

        const float4* src;
        if (p < FIRST_NEW_PAGE) {
            const int spage = __ldg(&pidx[b * PPS + p + SHIFT_PAGES]);
            src = (const float4*)cache + (size_t)spage * PAGE_F4 + HALF_F4 + chunk * CCHUNK_F4;
        } else if (p == LAST_PAGE) {
            src = (const float4*)cache + (size_t)dpage * PAGE_F4 + HALF_F4 + chunk * CCHUNK_F4;
        } else {
            src = (const float4*)vnew
                + (size_t)(b * SEQ + (p - FIRST_NEW_PAGE) * PAGE_SZ) * SLOT_F4 + chunk * CCHUNK_F4;
        }

        // 2048 f4 by 128 threads: one front-batched burst of 16 LDG.128
        float4 r[16];
        #pragma unroll
        for (int j = 0; j < 16; j++) r[j] = __ldcs(&src[tid + 128 * j]);
        #pragma unroll
        for (int j = 0; j < 16; j++) __stcs(&dst[tid + 128 * j], r[j]);
        return;
    }

    // ===== k-rope task: 16 KB, 2 slots, per-thread MLP=8 =====
    const int rr    = q3 * 2 + (r3 - 1);   // 0..8191
    const int i     = rr >> 3;             // logical page
    const int chunk = rr & 7;              // eighth of the k half
    const int b     = i >> 8;
    const int p     = i & 255;

    const int dpage = __ldg(&pidx[i]);
    float4* dst = (float4*)out + (size_t)dpage * PAGE_F4 + chunk * RCHUNK_F4;

    const float4* src;
    if (p < FIRST_NEW_PAGE) {
        const int spage = __ldg(&pidx[b * PPS + p + SHIFT_PAGES]);
        src = (const float4*)cache + (size_t)spage * PAGE_F4 + chunk * RCHUNK_F4;
    } else if (p == LAST_PAGE) {
        src = (const float4*)cache + (size_t)dpage * PAGE_F4 + chunk * RCHUNK_F4;
    } else {
        src = (const float4*)knew
            + (size_t)(b * SEQ + (p - FIRST_NEW_PAGE) * PAGE_SZ) * SLOT_F4 + chunk * RCHUNK_F4;
    }

    __shared__ __align__(16) float s_cos[2][64];
    __shared__ __align__(16) float s_sin[2][64];

    {
        // 2 slots * 64 freqs = 128 entries = one per thread
        const int slot = tid >> 6;
        const int f    = tid & 63;
        const float invf = (float)exp2(-(double)f * LOG2_THETA_OVER_64);  // f32-rounded inv_freq
        const float ang  = (float)(p * PAGE_SZ + chunk * 2 + slot) * invf;
        float s, c;
        sincosf(ang, &s, &c);
        s_cos[slot][f] = c;
        s_sin[slot][f] = s;
    }
    __syncthreads();

    // thread owns heads {h0, h0+8} for its j; front-batch all 8 loads
    const int h0 = tid >> 4;
    const int j  = tid & 15;

    float4 a[2][2], bb[2][2];
    #pragma unroll
    for (int q = 0; q < 2; q++) {         // slot
        #pragma unroll
        for (int e = 0; e < 2; e++) {     // head group
            const float4* sp = src + q * SLOT_F4 + (h0 + 8 * e) * HEAD_F4 + j;
            a[q][e]  = __ldcs(&sp[0]);    // x1 (dims 4j..4j+3)
            bb[q][e] = __ldcs(&sp[16]);   // x2 (dims 64+4j..)
        }
    }

    #pragma unroll
    for (int q = 0; q < 2; q++) {
        const float4 c = *(const float4*)&s_cos[q][4 * j];
        const float4 s = *(const float4*)&s_sin[q][4 * j];
        #pragma unroll
        for (int e = 0; e < 2; e++) {
            float4 o1, o2;
            o1.x = a[q][e].x * c.x - bb[q][e].x * s.x;  o2.x = a[q][e].x * s.x + bb[q][e].x * c.x;
            o1.y = a[q][e].y * c.y - bb[q][e].y * s.y;  o2.y = a[q][e].y * s.y + bb[q][e].y * c.y;
            o1.z = a[q][e].z * c.z - bb[q][e].z * s.z;  o2.z = a[q][e].z * s.z + bb[q][e].z * c.z;
            o1.w = a[q][e].w * c.w - bb[q][e].w * s.w;  o2.w = a[q][e].w * s.w + bb[q][e].w * c.w;

            float4* dp = dst + q * SLOT_F4 + (h0 + 8 * e) * HEAD_F4 + j;
            __stcs(&dp[0],  o1);
            __stcs(&dp[16], o2);
        }
    }
}

extern "C" void kernel_launch(void* const* d_in, const int* in_sizes, int n_in,
                              void* d_out, int out_size) {
    const float* k     = (const float*)d_in[0];
    const float* v     = (const float*)d_in[1];
    const float* cache = (const float*)d_in[2];
    const int*   pidx  = (const int*)d_in[3];
    float*       out   = (float*)d_out;

    kv_rotate_kernel<<<NTASKS, 128>>>(k, v, cache, pidx, out);
}